// round 16
// baseline (speedup 1.0000x reference)
#include <cuda_runtime.h>
#include <math.h>
#include <stdint.h>

#define NMAX 200000
#define B_   4
#define C2D  128
#define H_   96
#define W_   312
#define MID  128
#define C3D  64
#define BM   128
#define KC   16
// attfuse dynamic smem: A(32768) + B(4096) + sred(2176) + sa(128) + stats(256) floats
#define AF_SMEM_FLOATS (32768 + 4096 + 2176 + 128 + 256)
#define AF_SMEM_BYTES  (AF_SMEM_FLOATS * 4)

typedef unsigned long long ull;

__device__ __forceinline__ void fma2(ull& d, ull a, ull b) {
    asm("fma.rn.f32x2 %0, %1, %2, %0;" : "+l"(d) : "l"(a), "l"(b));
}
__device__ __forceinline__ ull dup2(float b) {
    ull r; asm("mov.b64 %0, {%1, %1};" : "=l"(r) : "f"(b)); return r;
}
__device__ __forceinline__ float ulo(ull a) { return __uint_as_float((unsigned)a); }
__device__ __forceinline__ float uhi(ull a) { return __uint_as_float((unsigned)(a >> 32)); }

__device__ __align__(16) float g_imgT[(size_t)B_ * H_ * W_ * C2D];
__device__ __align__(16) float g_hpre[(size_t)NMAX * MID];
__device__ __align__(16) float g_vfeat[(size_t)NMAX * MID];
__device__ __align__(16) float g_ifeat[(size_t)NMAX * C2D];
__device__ float g_stats[512];

// ---------------- K0: image transpose + stats zeroing ----------------
__global__ void k_transpose(const float* __restrict__ img) {
    __shared__ float tile[32][33];
    int bh = blockIdx.z, b = bh / H_, hh = bh % H_;
    int w0 = blockIdx.x * 32, c0 = blockIdx.y * 32;
    int tx = threadIdx.x, ty = threadIdx.y;
    if (blockIdx.x == 0 && blockIdx.y == 0 && blockIdx.z == 0) {
        int tt = ty * 32 + tx;
        g_stats[tt] = 0.f;
        g_stats[tt + 256] = 0.f;
    }
    #pragma unroll
    for (int i = 0; i < 32; i += 8) {
        int c = c0 + ty + i, w = w0 + tx;
        float v = 0.f;
        if (w < W_) v = img[((size_t)(b * C2D + c) * H_ + hh) * W_ + w];
        tile[ty + i][tx] = v;
    }
    __syncthreads();
    #pragma unroll
    for (int i = 0; i < 32; i += 8) {
        int w = w0 + ty + i, c = c0 + tx;
        if (w < W_) g_imgT[((size_t)bh * W_ + w) * C2D + c] = tile[tx][ty + i];
    }
}

// ---------------- shared GEMM pieces ----------------
__device__ __forceinline__ void ldg_frag(float4 f[2], const float* __restrict__ src,
                                         int ld, int base, int N, int kofs, int t) {
    #pragma unroll
    for (int i = 0; i < 2; i++) {
        int idx = i * 256 + t;
        int r = idx >> 2, k0 = (idx & 3) * 4;
        f[i] = make_float4(0.f, 0.f, 0.f, 0.f);
        if (base + r < N)
            f[i] = *reinterpret_cast<const float4*>(src + (size_t)(base + r) * ld + kofs + k0);
    }
}
__device__ __forceinline__ void sts_frag(float (*sT)[BM], const float4 f[2], int t) {
    #pragma unroll
    for (int i = 0; i < 2; i++) {
        int idx = i * 256 + t;
        int r = idx >> 2, k0 = (idx & 3) * 4;
        sT[k0][r] = f[i].x; sT[k0+1][r] = f[i].y; sT[k0+2][r] = f[i].z; sT[k0+3][r] = f[i].w;
    }
}
// f32x2 split-tile core: rows {tr4..+3, tr4+64..+67}, cols {tc4..+3, tc4+64..+67}
__device__ __forceinline__ void gemm_chunk(const float (*sAT)[BM], const float (*sBT)[BM],
                                           ull acc[8][4], int tr4, int tc4) {
    #pragma unroll
    for (int k = 0; k < KC; k++) {
        ulonglong2 aA = *reinterpret_cast<const ulonglong2*>(&sAT[k][tr4]);
        ulonglong2 aB = *reinterpret_cast<const ulonglong2*>(&sAT[k][tr4 + 64]);
        float4 b0 = *reinterpret_cast<const float4*>(&sBT[k][tc4]);
        float4 b1 = *reinterpret_cast<const float4*>(&sBT[k][tc4 + 64]);
        float bs[8] = {b0.x, b0.y, b0.z, b0.w, b1.x, b1.y, b1.z, b1.w};
        #pragma unroll
        for (int c = 0; c < 8; c++) {
            ull bd = dup2(bs[c]);
            fma2(acc[c][0], aA.x, bd); fma2(acc[c][1], aA.y, bd);
            fma2(acc[c][2], aB.x, bd); fma2(acc[c][3], aB.y, bd);
        }
    }
}
__device__ __forceinline__ void store_tile(float* __restrict__ dst, const ull acc[8][4],
                                           const float* __restrict__ bias,
                                           int base, int N, int tr4, int tc4) {
    float4 bb0 = *reinterpret_cast<const float4*>(bias + tc4);
    float4 bb1 = *reinterpret_cast<const float4*>(bias + tc4 + 64);
    float bv[8] = {bb0.x, bb0.y, bb0.z, bb0.w, bb1.x, bb1.y, bb1.z, bb1.w};
    #pragma unroll
    for (int p = 0; p < 4; p++) {
        int rl = (p < 2) ? tr4 + 2 * p : tr4 + 64 + 2 * (p - 2);
        int r0 = base + rl;
        if (r0 < N) {
            float4 f0 = make_float4(ulo(acc[0][p])+bv[0], ulo(acc[1][p])+bv[1], ulo(acc[2][p])+bv[2], ulo(acc[3][p])+bv[3]);
            float4 f1 = make_float4(ulo(acc[4][p])+bv[4], ulo(acc[5][p])+bv[5], ulo(acc[6][p])+bv[6], ulo(acc[7][p])+bv[7]);
            *reinterpret_cast<float4*>(dst + (size_t)r0 * 128 + tc4) = f0;
            *reinterpret_cast<float4*>(dst + (size_t)r0 * 128 + tc4 + 64) = f1;
        }
        if (r0 + 1 < N) {
            float4 f0 = make_float4(uhi(acc[0][p])+bv[0], uhi(acc[1][p])+bv[1], uhi(acc[2][p])+bv[2], uhi(acc[3][p])+bv[3]);
            float4 f1 = make_float4(uhi(acc[4][p])+bv[4], uhi(acc[5][p])+bv[5], uhi(acc[6][p])+bv[6], uhi(acc[7][p])+bv[7]);
            *reinterpret_cast<float4*>(dst + (size_t)(r0+1) * 128 + tc4) = f0;
            *reinterpret_cast<float4*>(dst + (size_t)(r0+1) * 128 + tc4 + 64) = f1;
        }
    }
}
__device__ __forceinline__ void store_tile_stats(float* __restrict__ dst, const ull acc[8][4],
                                                 const float* __restrict__ bias,
                                                 int base, int N, int tr4, int tc4,
                                                 float* sSum, float* sSq) {
    float4 bb0 = *reinterpret_cast<const float4*>(bias + tc4);
    float4 bb1 = *reinterpret_cast<const float4*>(bias + tc4 + 64);
    float bv[8] = {bb0.x, bb0.y, bb0.z, bb0.w, bb1.x, bb1.y, bb1.z, bb1.w};
    float cs[8] = {0,0,0,0,0,0,0,0}, cq[8] = {0,0,0,0,0,0,0,0};
    #pragma unroll
    for (int p = 0; p < 4; p++) {
        int rl = (p < 2) ? tr4 + 2 * p : tr4 + 64 + 2 * (p - 2);
        int r0 = base + rl;
        if (r0 < N) {
            float o[8];
            #pragma unroll
            for (int c = 0; c < 8; c++) { o[c] = ulo(acc[c][p]) + bv[c]; cs[c] += o[c]; cq[c] += o[c]*o[c]; }
            *reinterpret_cast<float4*>(dst + (size_t)r0 * 128 + tc4)      = make_float4(o[0],o[1],o[2],o[3]);
            *reinterpret_cast<float4*>(dst + (size_t)r0 * 128 + tc4 + 64) = make_float4(o[4],o[5],o[6],o[7]);
        }
        if (r0 + 1 < N) {
            float o[8];
            #pragma unroll
            for (int c = 0; c < 8; c++) { o[c] = uhi(acc[c][p]) + bv[c]; cs[c] += o[c]; cq[c] += o[c]*o[c]; }
            *reinterpret_cast<float4*>(dst + (size_t)(r0+1) * 128 + tc4)      = make_float4(o[0],o[1],o[2],o[3]);
            *reinterpret_cast<float4*>(dst + (size_t)(r0+1) * 128 + tc4 + 64) = make_float4(o[4],o[5],o[6],o[7]);
        }
    }
    #pragma unroll
    for (int c = 0; c < 8; c++) {
        int col = (c < 4) ? tc4 + c : tc4 + 64 + (c - 4);
        atomicAdd(&sSum[col], cs[c]);
        atomicAdd(&sSq[col],  cq[c]);
    }
}

#define GEMM_PROLOG() \
    int t = threadIdx.x; \
    int tc4 = (t & 15) * 4, tr4 = (t >> 4) * 4; \
    int base = blockIdx.x * BM; \
    ull acc[8][4]; \
    _Pragma("unroll") \
    for (int c = 0; c < 8; c++) { acc[c][0]=0; acc[c][1]=0; acc[c][2]=0; acc[c][3]=0; }

#define ACC_ZERO() \
    _Pragma("unroll") \
    for (int c = 0; c < 8; c++) { acc[c][0]=0; acc[c][1]=0; acc[c][2]=0; acc[c][3]=0; }

// ---------------- K1: hpre = vf @ w1^T + b1, + bn1 stats ----------------
__global__ __launch_bounds__(256, 2) void k_gemm1(const float* __restrict__ vf,
                                                  const float* __restrict__ w1,
                                                  const float* __restrict__ b1, int N) {
    __shared__ __align__(16) float sAT[2][KC][BM];
    __shared__ __align__(16) float sBT[2][KC][BM];
    __shared__ float sSum[128], sSq[128];
    GEMM_PROLOG();
    if (t < 128) { sSum[t] = 0.f; sSq[t] = 0.f; }
    const int nc = C3D / KC;
    float4 fa[2], fb[2];
    ldg_frag(fa, vf, C3D, base, N, 0, t);
    ldg_frag(fb, w1, C3D, 0, 1 << 30, 0, t);
    sts_frag(sAT[0], fa, t); sts_frag(sBT[0], fb, t);
    ldg_frag(fa, vf, C3D, base, N, KC, t);
    ldg_frag(fb, w1, C3D, 0, 1 << 30, KC, t);
    __syncthreads();
    for (int c = 0; c < nc; c++) {
        gemm_chunk(sAT[c & 1], sBT[c & 1], acc, tr4, tc4);
        if (c + 1 < nc) {
            sts_frag(sAT[(c+1)&1], fa, t); sts_frag(sBT[(c+1)&1], fb, t);
            if (c + 2 < nc) {
                ldg_frag(fa, vf, C3D, base, N, (c+2)*KC, t);
                ldg_frag(fb, w1, C3D, 0, 1 << 30, (c+2)*KC, t);
            }
            __syncthreads();
        }
    }
    store_tile_stats(g_hpre, acc, b1, base, N, tr4, tc4, sSum, sSq);
    __syncthreads();
    if (t < 128) {
        atomicAdd(&g_stats[t], sSum[t]);
        atomicAdd(&g_stats[128 + t], sSq[t]);
    }
}

// ---------------- K3: vfeat = relu(bn(hpre)) @ w2^T + b2 (bn from stats in prologue) ----------------
__global__ __launch_bounds__(256, 2) void k_gemm2(const float* __restrict__ w2,
                                                  const float* __restrict__ b2,
                                                  const float* __restrict__ bn1_g,
                                                  const float* __restrict__ bn1_b, int N) {
    __shared__ __align__(16) float sAT[2][KC][BM];
    __shared__ __align__(16) float sBT[2][KC][BM];
    __shared__ float sS[MID], sH[MID];
    GEMM_PROLOG();
    if (t < 128) {
        float invN = 1.f / (float)N;
        float m   = g_stats[t] * invN;
        float var = g_stats[128 + t] * invN - m * m;
        float s = __ldg(bn1_g + t) * rsqrtf(var + 1e-5f);
        sS[t] = s;
        sH[t] = __ldg(bn1_b + t) - m * s;
    }
    __syncthreads();
    const int nc = MID / KC;
    auto ldgA = [&](float4 f[2], int kofs) {
        ldg_frag(f, g_hpre, MID, base, N, kofs, t);
        #pragma unroll
        for (int i = 0; i < 2; i++) {
            int idx = i * 256 + t;
            int gk = kofs + (idx & 3) * 4;
            f[i].x = fmaxf(fmaf(f[i].x, sS[gk],   sH[gk]),   0.f);
            f[i].y = fmaxf(fmaf(f[i].y, sS[gk+1], sH[gk+1]), 0.f);
            f[i].z = fmaxf(fmaf(f[i].z, sS[gk+2], sH[gk+2]), 0.f);
            f[i].w = fmaxf(fmaf(f[i].w, sS[gk+3], sH[gk+3]), 0.f);
        }
    };
    float4 fa[2], fb[2];
    ldgA(fa, 0);
    ldg_frag(fb, w2, MID, 0, 1 << 30, 0, t);
    sts_frag(sAT[0], fa, t); sts_frag(sBT[0], fb, t);
    ldgA(fa, KC);
    ldg_frag(fb, w2, MID, 0, 1 << 30, KC, t);
    __syncthreads();
    for (int c = 0; c < nc; c++) {
        gemm_chunk(sAT[c & 1], sBT[c & 1], acc, tr4, tc4);
        if (c + 1 < nc) {
            sts_frag(sAT[(c+1)&1], fa, t); sts_frag(sBT[(c+1)&1], fb, t);
            if (c + 2 < nc) {
                ldgA(fa, (c+2)*KC);
                ldg_frag(fb, w2, MID, 0, 1 << 30, (c+2)*KC, t);
            }
            __syncthreads();
        }
    }
    store_tile(g_vfeat, acc, b2, base, N, tr4, tc4);
}

// ---------------- K4: projection + bilinear gather -> ifeat ----------------
__global__ __launch_bounds__(256) void k_sample(const int* __restrict__ coords,
                                                const float* __restrict__ P2, int N) {
    int j  = threadIdx.x & 127;
    int rr = threadIdx.x >> 7;
    int row0 = blockIdx.x * 64;
    for (int r = rr; r < 64; r += 2) {
        int row = row0 + r;
        if (row >= N) break;
        int4 c4 = __ldg(reinterpret_cast<const int4*>(coords + (size_t)row * 4));
        int b = c4.x;
        float p0 = (float)c4.y * 0.05f;
        float p1 = (float)c4.z * 0.05f - 40.f;
        float p2 = (float)c4.w * 0.1f  - 3.f;
        const float* P = P2 + b * 12;
        float cam0 = __ldg(P+0)*p0 + __ldg(P+1)*p1 + __ldg(P+2)*p2  + __ldg(P+3);
        float cam1 = __ldg(P+4)*p0 + __ldg(P+5)*p1 + __ldg(P+6)*p2  + __ldg(P+7);
        float cam2 = __ldg(P+8)*p0 + __ldg(P+9)*p1 + __ldg(P+10)*p2 + __ldg(P+11);
        float d = cam2 + 1e-8f;
        float u = cam0 / d, v = cam1 / d;
        float gx = u / (float)W_ * 2.f - 1.f; gx = fminf(fmaxf(gx, -1.f), 1.f);
        float gy = v / (float)H_ * 2.f - 1.f; gy = fminf(fmaxf(gy, -1.f), 1.f);
        float ix = ((gx + 1.f) * (float)W_ - 1.f) * 0.5f;
        float iy = ((gy + 1.f) * (float)H_ - 1.f) * 0.5f;
        float x0f = floorf(ix), y0f = floorf(iy);
        float wx = ix - x0f, wy = iy - y0f;
        int x0 = (int)x0f, y0 = (int)y0f;
        float acc = 0.f;
        #pragma unroll
        for (int cy = 0; cy < 2; cy++)
            #pragma unroll
            for (int cx = 0; cx < 2; cx++) {
                int yc = y0 + cy, xc = x0 + cx;
                float wgt = (cx ? wx : 1.f - wx) * (cy ? wy : 1.f - wy);
                if (xc >= 0 && xc < W_ && yc >= 0 && yc < H_)
                    acc = fmaf(wgt, g_imgT[(((size_t)(b * H_ + yc)) * W_ + xc) * C2D + j], acc);
            }
        g_ifeat[(size_t)row * C2D + j] = acc;
    }
}

// shared A loader for the concat [vfeat | ifeat]
__device__ __forceinline__ void ldg_cat(float4 f[2], int base, int N, int ck, int t) {
    const float* src = (ck < 128) ? g_vfeat : g_ifeat;
    int ko = (ck < 128) ? ck : ck - 128;
    ldg_frag(f, src, 128, base, N, ko, t);
}

// ---------------- K5+K6 merged, persistent-A in smem ----------------
__global__ __launch_bounds__(256, 1) void k_attfuse(const float* __restrict__ aw1,
                                                    const float* __restrict__ ab1,
                                                    const float* __restrict__ aw2,
                                                    const float* __restrict__ ab2,
                                                    const float* __restrict__ fw,
                                                    const float* __restrict__ fb,
                                                    float* __restrict__ out, int N) {
    extern __shared__ float dsm[];
    float* Afull = dsm;                                              // [256][128]
    float (*sBT)[KC][BM] = (float(*)[KC][BM])(dsm + 32768);          // double buf
    float (*sred)[17]    = (float(*)[17])(dsm + 32768 + 4096);       // [128][17]
    float* sa   = dsm + 32768 + 4096 + 2176;
    float* sSum = sa + 128;
    float* sSq  = sSum + 128;
    GEMM_PROLOG();
    if (t < 128) { sSum[t] = 0.f; sSq[t] = 0.f; }
    const int nc = 256 / KC;   // 16
    float4 fa[2], fb2[2];

    // ===== phase 1: attention GEMM; A persists in Afull =====
    ldg_cat(fa, base, N, 0, t);
    ldg_frag(fb2, aw1, 256, 0, 1 << 30, 0, t);
    sts_frag((float(*)[BM])(Afull), fa, t); sts_frag(sBT[0], fb2, t);
    ldg_cat(fa, base, N, KC, t);
    ldg_frag(fb2, aw1, 256, 0, 1 << 30, KC, t);
    __syncthreads();
    for (int c = 0; c < nc; c++) {
        gemm_chunk((const float(*)[BM])(Afull + c * KC * BM), sBT[c & 1], acc, tr4, tc4);
        if (c + 1 < nc) {
            sts_frag((float(*)[BM])(Afull + (c + 1) * KC * BM), fa, t);
            sts_frag(sBT[(c+1)&1], fb2, t);
            if (c + 2 < nc) {
                ldg_cat(fa, base, N, (c+2)*KC, t);
                ldg_frag(fb2, aw1, 256, 0, 1 << 30, (c+2)*KC, t);
            }
            __syncthreads();
        }
    }
    {   // attention epilogue -> sa
        float4 bb0 = *reinterpret_cast<const float4*>(ab1 + tc4);
        float4 bb1 = *reinterpret_cast<const float4*>(ab1 + tc4 + 64);
        float bv[8] = {bb0.x, bb0.y, bb0.z, bb0.w, bb1.x, bb1.y, bb1.z, bb1.w};
        float4 ww0 = *reinterpret_cast<const float4*>(aw2 + tc4);
        float4 ww1 = *reinterpret_cast<const float4*>(aw2 + tc4 + 64);
        float wv[8] = {ww0.x, ww0.y, ww0.z, ww0.w, ww1.x, ww1.y, ww1.z, ww1.w};
        __syncthreads();   // all reads of Afull chunk 15 done before epilogue writes sred
        #pragma unroll
        for (int p = 0; p < 4; p++) {
            int rl = (p < 2) ? tr4 + 2 * p : tr4 + 64 + 2 * (p - 2);
            float slo = 0.f, shi = 0.f;
            #pragma unroll
            for (int c = 0; c < 8; c++) {
                slo += fmaxf(ulo(acc[c][p]) + bv[c], 0.f) * wv[c];
                shi += fmaxf(uhi(acc[c][p]) + bv[c], 0.f) * wv[c];
            }
            sred[rl][t & 15]     = slo;
            sred[rl + 1][t & 15] = shi;
        }
        __syncthreads();
        if (t < 128) {
            float s = __ldg(ab2);
            #pragma unroll
            for (int i = 0; i < 16; i++) s += sred[t][i];
            sa[t] = 1.f / (1.f + expf(-s));
        }
        __syncthreads();
    }

    // ===== scale pass: Afull[k][r] *= (k<128 ? a[r] : 1-a[r]) =====
    #pragma unroll
    for (int i = 0; i < 128; i++) {
        int u = i * 256 + t;          // u = k*128 + r
        int r = u & 127;
        float a = sa[r];
        float m = (u < 16384) ? a : 1.f - a;
        Afull[u] *= m;
    }
    __syncthreads();

    // ===== phase 2: fused GEMM from persistent scaled A =====
    ACC_ZERO();
    ldg_frag(fb2, fw, 256, 0, 1 << 30, 0, t);
    sts_frag(sBT[0], fb2, t);
    ldg_frag(fb2, fw, 256, 0, 1 << 30, KC, t);
    __syncthreads();
    for (int c = 0; c < nc; c++) {
        gemm_chunk((const float(*)[BM])(Afull + c * KC * BM), sBT[c & 1], acc, tr4, tc4);
        if (c + 1 < nc) {
            sts_frag(sBT[(c+1)&1], fb2, t);
            if (c + 2 < nc)
                ldg_frag(fb2, fw, 256, 0, 1 << 30, (c+2)*KC, t);
            __syncthreads();
        }
    }
    store_tile_stats(out, acc, fb, base, N, tr4, tc4, sSum, sSq);
    __syncthreads();
    if (t < 128) {
        atomicAdd(&g_stats[256 + t], sSum[t]);
        atomicAdd(&g_stats[384 + t], sSq[t]);
    }
}

// ---------------- K8: in-place final bn + relu (bn from stats in prologue) ----------------
__global__ __launch_bounds__(256) void k_bnrelu(float* __restrict__ out,
                                                const float* __restrict__ bnf_g,
                                                const float* __restrict__ bnf_b,
                                                int N, long total4) {
    __shared__ float sc[128], sh[128];
    int t = threadIdx.x;
    if (t < 128) {
        float invN = 1.f / (float)N;
        float m   = g_stats[256 + t] * invN;
        float var = g_stats[384 + t] * invN - m * m;
        float s = __ldg(bnf_g + t) * rsqrtf(var + 1e-5f);
        sc[t] = s;
        sh[t] = __ldg(bnf_b + t) - m * s;
    }
    __syncthreads();
    long i = (long)blockIdx.x * blockDim.x + t;
    if (i < total4) {
        int cb = (int)((i & 31) * 4);
        float4 v = reinterpret_cast<float4*>(out)[i];
        v.x = fmaxf(fmaf(v.x, sc[cb],     sh[cb]),     0.f);
        v.y = fmaxf(fmaf(v.y, sc[cb + 1], sh[cb + 1]), 0.f);
        v.z = fmaxf(fmaf(v.z, sc[cb + 2], sh[cb + 2]), 0.f);
        v.w = fmaxf(fmaf(v.w, sc[cb + 3], sh[cb + 3]), 0.f);
        reinterpret_cast<float4*>(out)[i] = v;
    }
}

// ---------------- launch ----------------
extern "C" void kernel_launch(void* const* d_in, const int* in_sizes, int n_in,
                              void* d_out, int out_size) {
    const float* vf     = (const float*)d_in[0];
    const int*   coords = (const int*)  d_in[1];
    const float* img    = (const float*)d_in[2];
    const float* P2     = (const float*)d_in[3];
    const float* vt_w1  = (const float*)d_in[4];
    const float* vt_b1  = (const float*)d_in[5];
    const float* bn1_g  = (const float*)d_in[6];
    const float* bn1_b  = (const float*)d_in[7];
    const float* vt_w2  = (const float*)d_in[8];
    const float* vt_b2  = (const float*)d_in[9];
    const float* att_w1 = (const float*)d_in[10];
    const float* att_b1 = (const float*)d_in[11];
    const float* att_w2 = (const float*)d_in[12];
    const float* att_b2 = (const float*)d_in[13];
    const float* fus_w  = (const float*)d_in[14];
    const float* fus_b  = (const float*)d_in[15];
    const float* bnf_g  = (const float*)d_in[16];
    const float* bnf_b  = (const float*)d_in[17];

    int N = in_sizes[1] / 4;
    float* out = (float*)d_out;
    int nblk = (N + BM - 1) / BM;

    static int attr_set = 0;
    if (!attr_set) {
        cudaFuncSetAttribute(k_attfuse, cudaFuncAttributeMaxDynamicSharedMemorySize, AF_SMEM_BYTES);
        attr_set = 1;
    }

    k_transpose<<<dim3((W_ + 31) / 32, C2D / 32, B_ * H_), dim3(32, 8)>>>(img);
    k_gemm1<<<nblk, 256>>>(vf, vt_w1, vt_b1, N);
    k_gemm2<<<nblk, 256>>>(vt_w2, vt_b2, bn1_g, bn1_b, N);
    k_sample<<<(N + 63) / 64, 256>>>(coords, P2, N);
    k_attfuse<<<nblk, 256, AF_SMEM_BYTES>>>(att_w1, att_b1, att_w2, att_b2, fus_w, fus_b, out, N);
    long total4 = (long)N * 32;
    k_bnrelu<<<(unsigned)((total4 + 255) / 256), 256>>>(out, bnf_g, bnf_b, N, total4);
}

// round 17
// speedup vs baseline: 1.1511x; 1.1511x over previous
#include <cuda_runtime.h>
#include <math.h>
#include <stdint.h>

#define NMAX 200000
#define B_   4
#define C2D  128
#define H_   96
#define W_   312
#define MID  128
#define C3D  64
#define BM   128
#define KC   16

typedef unsigned long long ull;

__device__ __forceinline__ void fma2(ull& d, ull a, ull b) {
    asm("fma.rn.f32x2 %0, %1, %2, %0;" : "+l"(d) : "l"(a), "l"(b));
}
__device__ __forceinline__ ull dup2(float b) {
    ull r; asm("mov.b64 %0, {%1, %1};" : "=l"(r) : "f"(b)); return r;
}
__device__ __forceinline__ float ulo(ull a) { return __uint_as_float((unsigned)a); }
__device__ __forceinline__ float uhi(ull a) { return __uint_as_float((unsigned)(a >> 32)); }

__device__ __align__(16) float g_imgT[(size_t)B_ * H_ * W_ * C2D];
__device__ __align__(16) float g_hpre[(size_t)NMAX * MID];
__device__ __align__(16) float g_vfeat[(size_t)NMAX * MID];
__device__ __align__(16) float g_ifeat[(size_t)NMAX * C2D];
__device__ float g_stats[512];

// ---------------- K0: image transpose + stats zeroing ----------------
__global__ void k_transpose(const float* __restrict__ img) {
    __shared__ float tile[32][33];
    int bh = blockIdx.z, b = bh / H_, hh = bh % H_;
    int w0 = blockIdx.x * 32, c0 = blockIdx.y * 32;
    int tx = threadIdx.x, ty = threadIdx.y;
    if (blockIdx.x == 0 && blockIdx.y == 0 && blockIdx.z == 0) {
        int tt = ty * 32 + tx;
        g_stats[tt] = 0.f;
        g_stats[tt + 256] = 0.f;
    }
    #pragma unroll
    for (int i = 0; i < 32; i += 8) {
        int c = c0 + ty + i, w = w0 + tx;
        float v = 0.f;
        if (w < W_) v = img[((size_t)(b * C2D + c) * H_ + hh) * W_ + w];
        tile[ty + i][tx] = v;
    }
    __syncthreads();
    #pragma unroll
    for (int i = 0; i < 32; i += 8) {
        int w = w0 + ty + i, c = c0 + tx;
        if (w < W_) g_imgT[((size_t)bh * W_ + w) * C2D + c] = tile[tx][ty + i];
    }
}

// ---------------- shared GEMM pieces ----------------
__device__ __forceinline__ void ldg_frag(float4 f[2], const float* __restrict__ src,
                                         int ld, int base, int N, int kofs, int t) {
    #pragma unroll
    for (int i = 0; i < 2; i++) {
        int idx = i * 256 + t;
        int r = idx >> 2, k0 = (idx & 3) * 4;
        f[i] = make_float4(0.f, 0.f, 0.f, 0.f);
        if (base + r < N)
            f[i] = *reinterpret_cast<const float4*>(src + (size_t)(base + r) * ld + kofs + k0);
    }
}
__device__ __forceinline__ void sts_frag(float (*sT)[BM], const float4 f[2], int t) {
    #pragma unroll
    for (int i = 0; i < 2; i++) {
        int idx = i * 256 + t;
        int r = idx >> 2, k0 = (idx & 3) * 4;
        sT[k0][r] = f[i].x; sT[k0+1][r] = f[i].y; sT[k0+2][r] = f[i].z; sT[k0+3][r] = f[i].w;
    }
}
// f32x2 split-tile core
__device__ __forceinline__ void gemm_chunk(const float (*sAT)[BM], const float (*sBT)[BM],
                                           ull acc[8][4], int tr4, int tc4) {
    #pragma unroll
    for (int k = 0; k < KC; k++) {
        ulonglong2 aA = *reinterpret_cast<const ulonglong2*>(&sAT[k][tr4]);
        ulonglong2 aB = *reinterpret_cast<const ulonglong2*>(&sAT[k][tr4 + 64]);
        float4 b0 = *reinterpret_cast<const float4*>(&sBT[k][tc4]);
        float4 b1 = *reinterpret_cast<const float4*>(&sBT[k][tc4 + 64]);
        float bs[8] = {b0.x, b0.y, b0.z, b0.w, b1.x, b1.y, b1.z, b1.w};
        #pragma unroll
        for (int c = 0; c < 8; c++) {
            ull bd = dup2(bs[c]);
            fma2(acc[c][0], aA.x, bd); fma2(acc[c][1], aA.y, bd);
            fma2(acc[c][2], aB.x, bd); fma2(acc[c][3], aB.y, bd);
        }
    }
}
__device__ __forceinline__ void store_tile(float* __restrict__ dst, const ull acc[8][4],
                                           const float* __restrict__ bias,
                                           int base, int N, int tr4, int tc4) {
    float4 bb0 = *reinterpret_cast<const float4*>(bias + tc4);
    float4 bb1 = *reinterpret_cast<const float4*>(bias + tc4 + 64);
    float bv[8] = {bb0.x, bb0.y, bb0.z, bb0.w, bb1.x, bb1.y, bb1.z, bb1.w};
    #pragma unroll
    for (int p = 0; p < 4; p++) {
        int rl = (p < 2) ? tr4 + 2 * p : tr4 + 64 + 2 * (p - 2);
        int r0 = base + rl;
        if (r0 < N) {
            float4 f0 = make_float4(ulo(acc[0][p])+bv[0], ulo(acc[1][p])+bv[1], ulo(acc[2][p])+bv[2], ulo(acc[3][p])+bv[3]);
            float4 f1 = make_float4(ulo(acc[4][p])+bv[4], ulo(acc[5][p])+bv[5], ulo(acc[6][p])+bv[6], ulo(acc[7][p])+bv[7]);
            *reinterpret_cast<float4*>(dst + (size_t)r0 * 128 + tc4) = f0;
            *reinterpret_cast<float4*>(dst + (size_t)r0 * 128 + tc4 + 64) = f1;
        }
        if (r0 + 1 < N) {
            float4 f0 = make_float4(uhi(acc[0][p])+bv[0], uhi(acc[1][p])+bv[1], uhi(acc[2][p])+bv[2], uhi(acc[3][p])+bv[3]);
            float4 f1 = make_float4(uhi(acc[4][p])+bv[4], uhi(acc[5][p])+bv[5], uhi(acc[6][p])+bv[6], uhi(acc[7][p])+bv[7]);
            *reinterpret_cast<float4*>(dst + (size_t)(r0+1) * 128 + tc4) = f0;
            *reinterpret_cast<float4*>(dst + (size_t)(r0+1) * 128 + tc4 + 64) = f1;
        }
    }
}
__device__ __forceinline__ void store_tile_stats(float* __restrict__ dst, const ull acc[8][4],
                                                 const float* __restrict__ bias,
                                                 int base, int N, int tr4, int tc4,
                                                 float* sSum, float* sSq) {
    float4 bb0 = *reinterpret_cast<const float4*>(bias + tc4);
    float4 bb1 = *reinterpret_cast<const float4*>(bias + tc4 + 64);
    float bv[8] = {bb0.x, bb0.y, bb0.z, bb0.w, bb1.x, bb1.y, bb1.z, bb1.w};
    float cs[8] = {0,0,0,0,0,0,0,0}, cq[8] = {0,0,0,0,0,0,0,0};
    #pragma unroll
    for (int p = 0; p < 4; p++) {
        int rl = (p < 2) ? tr4 + 2 * p : tr4 + 64 + 2 * (p - 2);
        int r0 = base + rl;
        if (r0 < N) {
            float o[8];
            #pragma unroll
            for (int c = 0; c < 8; c++) { o[c] = ulo(acc[c][p]) + bv[c]; cs[c] += o[c]; cq[c] += o[c]*o[c]; }
            *reinterpret_cast<float4*>(dst + (size_t)r0 * 128 + tc4)      = make_float4(o[0],o[1],o[2],o[3]);
            *reinterpret_cast<float4*>(dst + (size_t)r0 * 128 + tc4 + 64) = make_float4(o[4],o[5],o[6],o[7]);
        }
        if (r0 + 1 < N) {
            float o[8];
            #pragma unroll
            for (int c = 0; c < 8; c++) { o[c] = uhi(acc[c][p]) + bv[c]; cs[c] += o[c]; cq[c] += o[c]*o[c]; }
            *reinterpret_cast<float4*>(dst + (size_t)(r0+1) * 128 + tc4)      = make_float4(o[0],o[1],o[2],o[3]);
            *reinterpret_cast<float4*>(dst + (size_t)(r0+1) * 128 + tc4 + 64) = make_float4(o[4],o[5],o[6],o[7]);
        }
    }
    #pragma unroll
    for (int c = 0; c < 8; c++) {
        int col = (c < 4) ? tc4 + c : tc4 + 64 + (c - 4);
        atomicAdd(&sSum[col], cs[c]);
        atomicAdd(&sSq[col],  cq[c]);
    }
}

#define GEMM_PROLOG() \
    int t = threadIdx.x; \
    int tc4 = (t & 15) * 4, tr4 = (t >> 4) * 4; \
    int base = blockIdx.x * BM; \
    ull acc[8][4]; \
    _Pragma("unroll") \
    for (int c = 0; c < 8; c++) { acc[c][0]=0; acc[c][1]=0; acc[c][2]=0; acc[c][3]=0; }

#define ACC_ZERO() \
    _Pragma("unroll") \
    for (int c = 0; c < 8; c++) { acc[c][0]=0; acc[c][1]=0; acc[c][2]=0; acc[c][3]=0; }

// ---------------- K1: hpre = vf @ w1^T + b1, + bn1 stats ----------------
__global__ __launch_bounds__(256, 2) void k_gemm1(const float* __restrict__ vf,
                                                  const float* __restrict__ w1,
                                                  const float* __restrict__ b1, int N) {
    __shared__ __align__(16) float sAT[2][KC][BM];
    __shared__ __align__(16) float sBT[2][KC][BM];
    __shared__ float sSum[128], sSq[128];
    GEMM_PROLOG();
    if (t < 128) { sSum[t] = 0.f; sSq[t] = 0.f; }
    const int nc = C3D / KC;
    float4 fa[2], fb[2];
    ldg_frag(fa, vf, C3D, base, N, 0, t);
    ldg_frag(fb, w1, C3D, 0, 1 << 30, 0, t);
    sts_frag(sAT[0], fa, t); sts_frag(sBT[0], fb, t);
    ldg_frag(fa, vf, C3D, base, N, KC, t);
    ldg_frag(fb, w1, C3D, 0, 1 << 30, KC, t);
    __syncthreads();
    for (int c = 0; c < nc; c++) {
        gemm_chunk(sAT[c & 1], sBT[c & 1], acc, tr4, tc4);
        if (c + 1 < nc) {
            sts_frag(sAT[(c+1)&1], fa, t); sts_frag(sBT[(c+1)&1], fb, t);
            if (c + 2 < nc) {
                ldg_frag(fa, vf, C3D, base, N, (c+2)*KC, t);
                ldg_frag(fb, w1, C3D, 0, 1 << 30, (c+2)*KC, t);
            }
            __syncthreads();
        }
    }
    store_tile_stats(g_hpre, acc, b1, base, N, tr4, tc4, sSum, sSq);
    __syncthreads();
    if (t < 128) {
        atomicAdd(&g_stats[t], sSum[t]);
        atomicAdd(&g_stats[128 + t], sSq[t]);
    }
}

// ---------------- K3: vfeat = relu(bn(hpre)) @ w2^T + b2 (bn from stats) ----------------
__global__ __launch_bounds__(256, 2) void k_gemm2(const float* __restrict__ w2,
                                                  const float* __restrict__ b2,
                                                  const float* __restrict__ bn1_g,
                                                  const float* __restrict__ bn1_b, int N) {
    __shared__ __align__(16) float sAT[2][KC][BM];
    __shared__ __align__(16) float sBT[2][KC][BM];
    __shared__ float sS[MID], sH[MID];
    GEMM_PROLOG();
    if (t < 128) {
        float invN = 1.f / (float)N;
        float m   = g_stats[t] * invN;
        float var = g_stats[128 + t] * invN - m * m;
        float s = __ldg(bn1_g + t) * rsqrtf(var + 1e-5f);
        sS[t] = s;
        sH[t] = __ldg(bn1_b + t) - m * s;
    }
    __syncthreads();
    const int nc = MID / KC;
    auto ldgA = [&](float4 f[2], int kofs) {
        ldg_frag(f, g_hpre, MID, base, N, kofs, t);
        #pragma unroll
        for (int i = 0; i < 2; i++) {
            int idx = i * 256 + t;
            int gk = kofs + (idx & 3) * 4;
            f[i].x = fmaxf(fmaf(f[i].x, sS[gk],   sH[gk]),   0.f);
            f[i].y = fmaxf(fmaf(f[i].y, sS[gk+1], sH[gk+1]), 0.f);
            f[i].z = fmaxf(fmaf(f[i].z, sS[gk+2], sH[gk+2]), 0.f);
            f[i].w = fmaxf(fmaf(f[i].w, sS[gk+3], sH[gk+3]), 0.f);
        }
    };
    float4 fa[2], fb[2];
    ldgA(fa, 0);
    ldg_frag(fb, w2, MID, 0, 1 << 30, 0, t);
    sts_frag(sAT[0], fa, t); sts_frag(sBT[0], fb, t);
    ldgA(fa, KC);
    ldg_frag(fb, w2, MID, 0, 1 << 30, KC, t);
    __syncthreads();
    for (int c = 0; c < nc; c++) {
        gemm_chunk(sAT[c & 1], sBT[c & 1], acc, tr4, tc4);
        if (c + 1 < nc) {
            sts_frag(sAT[(c+1)&1], fa, t); sts_frag(sBT[(c+1)&1], fb, t);
            if (c + 2 < nc) {
                ldgA(fa, (c+2)*KC);
                ldg_frag(fb, w2, MID, 0, 1 << 30, (c+2)*KC, t);
            }
            __syncthreads();
        }
    }
    store_tile(g_vfeat, acc, b2, base, N, tr4, tc4);
}

// ---------------- K4: projection (once per row) + vectorized gather ----------------
__global__ __launch_bounds__(256) void k_sample(const int* __restrict__ coords,
                                                const float* __restrict__ P2, int N) {
    __shared__ float sw[64][4];
    __shared__ int   so[64][4];
    int t = threadIdx.x;
    int row0 = blockIdx.x * 64;
    if (t < 64) {
        int row = row0 + t;
        float w[4] = {0.f, 0.f, 0.f, 0.f};
        int   o[4] = {0, 0, 0, 0};
        if (row < N) {
            int4 c4 = __ldg(reinterpret_cast<const int4*>(coords + (size_t)row * 4));
            int b = c4.x;
            float p0 = (float)c4.y * 0.05f;
            float p1 = (float)c4.z * 0.05f - 40.f;
            float p2 = (float)c4.w * 0.1f  - 3.f;
            const float* P = P2 + b * 12;
            float cam0 = __ldg(P+0)*p0 + __ldg(P+1)*p1 + __ldg(P+2)*p2  + __ldg(P+3);
            float cam1 = __ldg(P+4)*p0 + __ldg(P+5)*p1 + __ldg(P+6)*p2  + __ldg(P+7);
            float cam2 = __ldg(P+8)*p0 + __ldg(P+9)*p1 + __ldg(P+10)*p2 + __ldg(P+11);
            float d = cam2 + 1e-8f;
            float u = cam0 / d, v = cam1 / d;
            float gx = u / (float)W_ * 2.f - 1.f; gx = fminf(fmaxf(gx, -1.f), 1.f);
            float gy = v / (float)H_ * 2.f - 1.f; gy = fminf(fmaxf(gy, -1.f), 1.f);
            float ix = ((gx + 1.f) * (float)W_ - 1.f) * 0.5f;
            float iy = ((gy + 1.f) * (float)H_ - 1.f) * 0.5f;
            float x0f = floorf(ix), y0f = floorf(iy);
            float wx = ix - x0f, wy = iy - y0f;
            int x0 = (int)x0f, y0 = (int)y0f;
            #pragma unroll
            for (int cy = 0; cy < 2; cy++)
                #pragma unroll
                for (int cx = 0; cx < 2; cx++) {
                    int yc = y0 + cy, xc = x0 + cx;
                    bool valid = (xc >= 0 && xc < W_ && yc >= 0 && yc < H_);
                    int idx = cy * 2 + cx;
                    w[idx] = valid ? (cx ? wx : 1.f - wx) * (cy ? wy : 1.f - wy) : 0.f;
                    o[idx] = valid ? ((b * H_ + yc) * W_ + xc) * C2D : 0;
                }
        }
        sw[t][0] = w[0]; sw[t][1] = w[1]; sw[t][2] = w[2]; sw[t][3] = w[3];
        so[t][0] = o[0]; so[t][1] = o[1]; so[t][2] = o[2]; so[t][3] = o[3];
    }
    __syncthreads();
    #pragma unroll
    for (int i = 0; i < 8; i++) {
        int u = i * 256 + t;           // 64 rows x 32 float4 chunks
        int r = u >> 5, c4i = (u & 31) * 4;
        int row = row0 + r;
        if (row < N) {
            float4 acc = make_float4(0.f, 0.f, 0.f, 0.f);
            #pragma unroll
            for (int c = 0; c < 4; c++) {
                float w = sw[r][c];
                float4 v = *reinterpret_cast<const float4*>(g_imgT + so[r][c] + c4i);
                acc.x = fmaf(w, v.x, acc.x);
                acc.y = fmaf(w, v.y, acc.y);
                acc.z = fmaf(w, v.z, acc.z);
                acc.w = fmaf(w, v.w, acc.w);
            }
            *reinterpret_cast<float4*>(g_ifeat + (size_t)row * C2D + c4i) = acc;
        }
    }
}

// shared A loader for the concat [vfeat | ifeat]
__device__ __forceinline__ void ldg_cat(float4 f[2], int base, int N, int ck, int t) {
    const float* src = (ck < 128) ? g_vfeat : g_ifeat;
    int ko = (ck < 128) ? ck : ck - 128;
    ldg_frag(f, src, 128, base, N, ko, t);
}

// ---------------- K5+K6 merged: attention then fused GEMM + bnf stats ----------------
__global__ __launch_bounds__(256, 2) void k_attfuse(const float* __restrict__ aw1,
                                                    const float* __restrict__ ab1,
                                                    const float* __restrict__ aw2,
                                                    const float* __restrict__ ab2,
                                                    const float* __restrict__ fw,
                                                    const float* __restrict__ fb,
                                                    float* __restrict__ out, int N) {
    __shared__ __align__(16) float sAT[2][KC][BM];
    __shared__ __align__(16) float sBT[2][KC][BM];
    __shared__ float sred[BM][17];
    __shared__ float sa[BM];
    __shared__ float sSum[128], sSq[128];
    GEMM_PROLOG();
    if (t < 128) { sSum[t] = 0.f; sSq[t] = 0.f; }
    const int nc = 256 / KC;
    float4 fa[2], fb2[2];

    // phase 1: attention GEMM
    ldg_cat(fa, base, N, 0, t);
    ldg_frag(fb2, aw1, 256, 0, 1 << 30, 0, t);
    sts_frag(sAT[0], fa, t); sts_frag(sBT[0], fb2, t);
    ldg_cat(fa, base, N, KC, t);
    ldg_frag(fb2, aw1, 256, 0, 1 << 30, KC, t);
    __syncthreads();
    for (int c = 0; c < nc; c++) {
        gemm_chunk(sAT[c & 1], sBT[c & 1], acc, tr4, tc4);
        if (c + 1 < nc) {
            sts_frag(sAT[(c+1)&1], fa, t); sts_frag(sBT[(c+1)&1], fb2, t);
            if (c + 2 < nc) {
                ldg_cat(fa, base, N, (c+2)*KC, t);
                ldg_frag(fb2, aw1, 256, 0, 1 << 30, (c+2)*KC, t);
            }
            __syncthreads();
        }
    }
    {   // attention epilogue -> sa
        float4 bb0 = *reinterpret_cast<const float4*>(ab1 + tc4);
        float4 bb1 = *reinterpret_cast<const float4*>(ab1 + tc4 + 64);
        float bv[8] = {bb0.x, bb0.y, bb0.z, bb0.w, bb1.x, bb1.y, bb1.z, bb1.w};
        float4 ww0 = *reinterpret_cast<const float4*>(aw2 + tc4);
        float4 ww1 = *reinterpret_cast<const float4*>(aw2 + tc4 + 64);
        float wv[8] = {ww0.x, ww0.y, ww0.z, ww0.w, ww1.x, ww1.y, ww1.z, ww1.w};
        #pragma unroll
        for (int p = 0; p < 4; p++) {
            int rl = (p < 2) ? tr4 + 2 * p : tr4 + 64 + 2 * (p - 2);
            float slo = 0.f, shi = 0.f;
            #pragma unroll
            for (int c = 0; c < 8; c++) {
                slo += fmaxf(ulo(acc[c][p]) + bv[c], 0.f) * wv[c];
                shi += fmaxf(uhi(acc[c][p]) + bv[c], 0.f) * wv[c];
            }
            sred[rl][t & 15]     = slo;
            sred[rl + 1][t & 15] = shi;
        }
        __syncthreads();
        if (t < 128) {
            float s = __ldg(ab2);
            #pragma unroll
            for (int i = 0; i < 16; i++) s += sred[t][i];
            sa[t] = 1.f / (1.f + expf(-s));
        }
        __syncthreads();
    }

    // phase 2: fused GEMM with attention-scaled A
    ACC_ZERO();
    auto ldgA = [&](float4 f[2], int ck) {
        ldg_cat(f, base, N, ck, t);
        bool isv = (ck < 128);
        #pragma unroll
        for (int i = 0; i < 2; i++) {
            int idx = i * 256 + t;
            int r = idx >> 2;
            float a = sa[r];
            float m = isv ? a : 1.f - a;
            f[i].x *= m; f[i].y *= m; f[i].z *= m; f[i].w *= m;
        }
    };
    ldgA(fa, 0);
    ldg_frag(fb2, fw, 256, 0, 1 << 30, 0, t);
    sts_frag(sAT[0], fa, t); sts_frag(sBT[0], fb2, t);
    ldgA(fa, KC);
    ldg_frag(fb2, fw, 256, 0, 1 << 30, KC, t);
    __syncthreads();
    for (int c = 0; c < nc; c++) {
        gemm_chunk(sAT[c & 1], sBT[c & 1], acc, tr4, tc4);
        if (c + 1 < nc) {
            sts_frag(sAT[(c+1)&1], fa, t); sts_frag(sBT[(c+1)&1], fb2, t);
            if (c + 2 < nc) {
                ldgA(fa, (c+2)*KC);
                ldg_frag(fb2, fw, 256, 0, 1 << 30, (c+2)*KC, t);
            }
            __syncthreads();
        }
    }
    store_tile_stats(out, acc, fb, base, N, tr4, tc4, sSum, sSq);
    __syncthreads();
    if (t < 128) {
        atomicAdd(&g_stats[256 + t], sSum[t]);
        atomicAdd(&g_stats[384 + t], sSq[t]);
    }
}

// ---------------- K8: in-place final bn + relu (bn from stats) ----------------
__global__ __launch_bounds__(256) void k_bnrelu(float* __restrict__ out,
                                                const float* __restrict__ bnf_g,
                                                const float* __restrict__ bnf_b,
                                                int N, long total4) {
    __shared__ float sc[128], sh[128];
    int t = threadIdx.x;
    if (t < 128) {
        float invN = 1.f / (float)N;
        float m   = g_stats[256 + t] * invN;
        float var = g_stats[384 + t] * invN - m * m;
        float s = __ldg(bnf_g + t) * rsqrtf(var + 1e-5f);
        sc[t] = s;
        sh[t] = __ldg(bnf_b + t) - m * s;
    }
    __syncthreads();
    long i = (long)blockIdx.x * blockDim.x + t;
    if (i < total4) {
        int cb = (int)((i & 31) * 4);
        float4 v = reinterpret_cast<float4*>(out)[i];
        v.x = fmaxf(fmaf(v.x, sc[cb],     sh[cb]),     0.f);
        v.y = fmaxf(fmaf(v.y, sc[cb + 1], sh[cb + 1]), 0.f);
        v.z = fmaxf(fmaf(v.z, sc[cb + 2], sh[cb + 2]), 0.f);
        v.w = fmaxf(fmaf(v.w, sc[cb + 3], sh[cb + 3]), 0.f);
        reinterpret_cast<float4*>(out)[i] = v;
    }
}

// ---------------- launch ----------------
extern "C" void kernel_launch(void* const* d_in, const int* in_sizes, int n_in,
                              void* d_out, int out_size) {
    const float* vf     = (const float*)d_in[0];
    const int*   coords = (const int*)  d_in[1];
    const float* img    = (const float*)d_in[2];
    const float* P2     = (const float*)d_in[3];
    const float* vt_w1  = (const float*)d_in[4];
    const float* vt_b1  = (const float*)d_in[5];
    const float* bn1_g  = (const float*)d_in[6];
    const float* bn1_b  = (const float*)d_in[7];
    const float* vt_w2  = (const float*)d_in[8];
    const float* vt_b2  = (const float*)d_in[9];
    const float* att_w1 = (const float*)d_in[10];
    const float* att_b1 = (const float*)d_in[11];
    const float* att_w2 = (const float*)d_in[12];
    const float* att_b2 = (const float*)d_in[13];
    const float* fus_w  = (const float*)d_in[14];
    const float* fus_b  = (const float*)d_in[15];
    const float* bnf_g  = (const float*)d_in[16];
    const float* bnf_b  = (const float*)d_in[17];

    int N = in_sizes[1] / 4;
    float* out = (float*)d_out;
    int nblk = (N + BM - 1) / BM;

    k_transpose<<<dim3((W_ + 31) / 32, C2D / 32, B_ * H_), dim3(32, 8)>>>(img);
    k_gemm1<<<nblk, 256>>>(vf, vt_w1, vt_b1, N);
    k_gemm2<<<nblk, 256>>>(vt_w2, vt_b2, bn1_g, bn1_b, N);
    k_sample<<<(N + 63) / 64, 256>>>(coords, P2, N);
    k_attfuse<<<nblk, 256>>>(att_w1, att_b1, att_w2, att_b2, fus_w, fus_b, out, N);
    long total4 = (long)N * 32;
    k_bnrelu<<<(unsigned)((total4 + 255) / 256), 256>>>(out, bnf_g, bnf_b, N, total4);
}